// round 13
// baseline (speedup 1.0000x reference)
#include <cuda_runtime.h>
#include <cuda.h>
#include <cuda_fp16.h>
#include <math.h>
#include <cstdint>

#define NN   20000
#define EE   320000
#define ETOT 340000
#define FIN  384
#define F1   1024
#define HH1  4
#define HD   256
#define F2   256
#define PHID 128
#define NSPLIT 10112          // 79 row tiles of 128; divisible by 4
#define TLO 79
#define THI 78

// ---------------- scratch (static device globals; no runtime alloc) ----------
__device__ float g_yp[NN];
__device__ float g_ss1[NN * HH1];
__device__ float g_sd1[NN * HH1];
__device__ float g_ss2[NN];
__device__ float g_sd2[NN];
__device__ float g_wa[8 * FIN];       // [h*2+{src,dst}][k]
__device__ int   g_deg[NN];
__device__ int   g_off[NN + 1];
__device__ int   g_cur[NN];
__device__ int   g_csrc[ETOT];
// fp16 planes
__device__ __align__(128) __half g_xh  [(size_t)NN * FIN];
__device__ __align__(128) __half g_aggx[(size_t)4 * NN * FIN];   // per-head agg of x
__device__ __align__(128) __half g_w1h4[(size_t)4 * 256 * FIN];  // per-head W1^T
__device__ __align__(128) __half g_o1h [(size_t)NN * F1];
__device__ __align__(128) __half g_w2h [(size_t)F2 * F1];
__device__ __align__(128) __half g_h2h [(size_t)NN * F2];
__device__ __align__(128) __half g_hh  [(size_t)NN * F2];
__device__ __align__(128) __half g_wph [(size_t)PHID * F2];

// ---------------- helpers ----------------
__device__ __forceinline__ uint32_t smem_u32(const void* p) {
    uint32_t a;
    asm("{ .reg .u64 t; cvta.to.shared.u64 t, %1; cvt.u32.u64 %0, t; }" : "=r"(a) : "l"(p));
    return a;
}
__device__ __forceinline__ void ldm4(uint32_t* r, uint32_t a) {
    asm volatile("ldmatrix.sync.aligned.m8n8.x4.shared.b16 {%0,%1,%2,%3}, [%4];"
                 : "=r"(r[0]), "=r"(r[1]), "=r"(r[2]), "=r"(r[3]) : "r"(a));
}
__device__ __forceinline__ void mma16816(float* c, const uint32_t* a, uint32_t b0, uint32_t b1) {
    asm volatile("mma.sync.aligned.m16n8k16.row.col.f32.f16.f16.f32 "
                 "{%0,%1,%2,%3}, {%4,%5,%6,%7}, {%8,%9}, {%0,%1,%2,%3};"
                 : "+f"(c[0]), "+f"(c[1]), "+f"(c[2]), "+f"(c[3])
                 : "r"(a[0]), "r"(a[1]), "r"(a[2]), "r"(a[3]), "r"(b0), "r"(b1));
}
#define MBARRIER_INIT(mb, c) \
    asm volatile("mbarrier.init.shared.b64 [%0], %1;" :: "r"((uint32_t)(mb)), "r"((uint32_t)(c)) : "memory")
#define MBARRIER_EXPECT_TX(mb, b) \
    asm volatile("mbarrier.arrive.expect_tx.shared.b64 _, [%0], %1;" \
                 :: "r"((uint32_t)(mb)), "r"((uint32_t)(b)) : "memory")
#define MBARRIER_WAIT_PARITY(mb, par) do { \
    uint32_t _m = (uint32_t)(mb), _p = (uint32_t)(par), _d; \
    asm volatile("{\n\t.reg .pred p;\n\t" \
        "mbarrier.try_wait.parity.acquire.cta.shared::cta.b64 p, [%1], %2;\n\t" \
        "selp.b32 %0, 1, 0, p;\n\t}" : "=r"(_d) : "r"(_m), "r"(_p) : "memory"); \
    if (!_d) { \
        asm volatile("{\n\t.reg .pred P1;\n\tWL_%=:\n\t" \
            "mbarrier.try_wait.parity.acquire.cta.shared::cta.b64 P1, [%0], %1, 0x989680;\n\t" \
            "@P1 bra.uni WD_%=;\n\tbra.uni WL_%=;\n\tWD_%=:\n\t}" \
            :: "r"(_m), "r"(_p) : "memory"); \
    } } while (0)
__device__ __forceinline__ void tma2d(uint32_t dst, const void* map, int x, int y, uint32_t mb) {
    asm volatile(
        "cp.async.bulk.tensor.2d.shared::cta.global.tile.mbarrier::complete_tx::bytes "
        "[%0], [%1, {%2, %3}], [%4];"
        :: "r"(dst), "l"(map), "r"(x), "r"(y), "r"(mb) : "memory");
}
#define SW128(o) ((o) ^ (((o) >> 3) & 0x70u))
__device__ __forceinline__ float lrelu(float x) { return x > 0.f ? x : 0.2f * x; }

// ---------------- small prep kernels ----------------
__global__ void k_cast(const float* __restrict__ in, __half* __restrict__ o, int total) {
    int i = blockIdx.x * blockDim.x + threadIdx.x;
    if (i < total) o[i] = __float2half_rn(in[i]);
}
__global__ void k_castT(const float* __restrict__ W, __half* __restrict__ o, int K, int N) {
    int i = blockIdx.x * blockDim.x + threadIdx.x;
    if (i >= K * N) return;
    int k = i / N, n = i % N;
    o[(size_t)n * K + k] = __float2half_rn(W[i]);
}
// W1 [FIN,F1] -> 4 per-head transposed planes [256, FIN]
__global__ void k_castT4(const float* __restrict__ W1, __half* __restrict__ o) {
    int i = blockIdx.x * blockDim.x + threadIdx.x;
    if (i >= FIN * F1) return;
    int k = i / F1, n = i % F1;
    int h = n >> 8, c = n & 255;
    o[(size_t)h * (256 * FIN) + (size_t)c * FIN + k] = __float2half_rn(W1[i]);
}
__global__ void k_zero3(float* c, float* d, float* e, int n) {
    int i = blockIdx.x * blockDim.x + threadIdx.x;
    if (i < n) { c[i] = 0.f; d[i] = 0.f; e[i] = 0.f; }
}
// wa[j][k] = sum_c W1[k, h*256+c] * a[h][c], j = h*2 + {src,dst}
__global__ void k_wa1(const float* __restrict__ W1, const float* __restrict__ as1,
                      const float* __restrict__ ad1, float* __restrict__ wa) {
    int i = blockIdx.x * blockDim.x + threadIdx.x;
    if (i >= 8 * FIN) return;
    int j = i / FIN, k = i % FIN;
    int h = j >> 1;
    const float* av = (j & 1) ? ad1 : as1;
    float s = 0.f;
    for (int c = 0; c < HD; c++) s += W1[(size_t)k * F1 + h * HD + c] * av[h * HD + c];
    wa[(size_t)j * FIN + k] = s;
}
// ss1/sd1 = x @ wa^T  (warp per node)
__global__ void k_slogits_x(const float* __restrict__ x, const float* __restrict__ wa,
                            float* __restrict__ ss, float* __restrict__ sd) {
    int w = (blockIdx.x * blockDim.x + threadIdx.x) >> 5;
    int lane = threadIdx.x & 31;
    if (w >= NN) return;
    float s[8] = {0, 0, 0, 0, 0, 0, 0, 0};
    const float* row = x + (size_t)w * FIN;
    for (int k = lane; k < FIN; k += 32) {
        float xv = row[k];
#pragma unroll
        for (int j = 0; j < 8; j++) s[j] += xv * wa[j * FIN + k];
    }
#pragma unroll
    for (int j = 0; j < 8; j++)
#pragma unroll
        for (int o = 16; o; o >>= 1) s[j] += __shfl_xor_sync(0xffffffffu, s[j], o);
    if (lane == 0) {
#pragma unroll
        for (int h = 0; h < 4; h++) { ss[w * 4 + h] = s[2 * h]; sd[w * 4 + h] = s[2 * h + 1]; }
    }
}

// ============== TMA HMMA GEMM: C[M,N] = A[M,K] @ B[N,K]^T ====================
// Outputs with row stride ldc. Optional: ebias (bias+ELU before store),
// fused attention logits (ss..), fused influence partial (yp..).
#define TG_STAGE 32768
#define TG_SMEM (1024 + 3 * TG_STAGE)

__global__ void __launch_bounds__(256, 2)
hgemm_tma(const __grid_constant__ CUtensorMap mA,
          const __grid_constant__ CUtensorMap mB,
          float* __restrict__ C, __half* __restrict__ Ch,
          int M, int N, int K, int ytile0, int ldc,
          const float* __restrict__ ebias,
          float* __restrict__ ss, float* __restrict__ sd,
          const float* __restrict__ av, const float* __restrict__ bv,
          float* __restrict__ yp, const float* __restrict__ bp1,
          const float* __restrict__ wp2) {
    extern __shared__ unsigned char smraw[];
    const uint32_t base0 = (smem_u32(smraw) + 1023u) & ~1023u;
    const uint32_t mbb = base0;
    const uint32_t tile0 = base0 + 1024;
    const int tid = threadIdx.x, wid = tid >> 5, lane = tid & 31;
    const int bm = (blockIdx.y + ytile0) * 128, bn = blockIdx.x * 128;
    const int wr = (wid >> 1) * 32, wn = (wid & 1) * 64;
    const int nc = K >> 6;

    if (tid == 0) {
        MBARRIER_INIT(mbb + 0, 1);
        MBARRIER_INIT(mbb + 8, 1);
        MBARRIER_INIT(mbb + 16, 1);
    }
    __syncthreads();

    if (tid == 0) {
#pragma unroll
        for (int s = 0; s < 2; s++) {
            uint32_t mb = mbb + 8u * s;
            uint32_t t = tile0 + (uint32_t)s * TG_STAGE;
            MBARRIER_EXPECT_TX(mb, TG_STAGE);
            tma2d(t,          &mA, s * 64, bm, mb);
            tma2d(t + 16384u, &mB, s * 64, bn, mb);
        }
    }

    float acc[2][8][4];
#pragma unroll
    for (int a = 0; a < 2; a++)
#pragma unroll
        for (int b = 0; b < 8; b++)
#pragma unroll
            for (int c = 0; c < 4; c++) acc[a][b][c] = 0.f;

    for (int i = 0; i < nc; i++) {
        const int b = i % 3;
        MBARRIER_WAIT_PARITY(mbb + 8u * b, (i / 3) & 1);
        __syncthreads();
        if (tid == 0 && i + 2 < nc) {
            const int nb = (i + 2) % 3;
            uint32_t mb = mbb + 8u * nb;
            uint32_t t = tile0 + (uint32_t)nb * TG_STAGE;
            MBARRIER_EXPECT_TX(mb, TG_STAGE);
            tma2d(t,          &mA, (i + 2) * 64, bm, mb);
            tma2d(t + 16384u, &mB, (i + 2) * 64, bn, mb);
        }

        const uint32_t tA = tile0 + (uint32_t)b * TG_STAGE;
        const uint32_t tB = tA + 16384u;
        const int gq = lane >> 3;
#pragma unroll
        for (int ks = 0; ks < 4; ks++) {
            uint32_t ar[2][4], br[4][4];
#pragma unroll
            for (int mt = 0; mt < 2; mt++) {
                uint32_t lin = (uint32_t)(wr + mt * 16 + (lane & 15)) * 128u
                             + (uint32_t)(ks * 32 + (lane >> 4) * 16);
                ldm4(ar[mt], tA + SW128(lin));
            }
#pragma unroll
            for (int bt = 0; bt < 4; bt++) {
                uint32_t lin = (uint32_t)(wn + bt * 16 + ((gq >> 1) << 3) + (lane & 7)) * 128u
                             + (uint32_t)(ks * 32 + (gq & 1) * 16);
                ldm4(br[bt], tB + SW128(lin));
            }
#pragma unroll
            for (int mt = 0; mt < 2; mt++)
#pragma unroll
                for (int j = 0; j < 8; j++) {
                    const int bt = j >> 1, p0 = (j & 1) * 2;
                    mma16816(acc[mt][j], ar[mt], br[bt][p0], br[bt][p0 + 1]);
                }
        }
    }

    // epilogue stores (optional bias+ELU)
#pragma unroll
    for (int mt = 0; mt < 2; mt++) {
        int m0 = bm + wr + mt * 16 + (lane >> 2);
#pragma unroll
        for (int j = 0; j < 8; j++) {
            int n0 = bn + wn + j * 8 + (lane & 3) * 2;
            float v0 = acc[mt][j][0], v1 = acc[mt][j][1];
            float v2 = acc[mt][j][2], v3 = acc[mt][j][3];
            if (ebias) {
                float b0 = ebias[n0], b1e = ebias[n0 + 1];
                v0 += b0; v1 += b1e; v2 += b0; v3 += b1e;
                v0 = v0 > 0.f ? v0 : expm1f(v0);
                v1 = v1 > 0.f ? v1 : expm1f(v1);
                v2 = v2 > 0.f ? v2 : expm1f(v2);
                v3 = v3 > 0.f ? v3 : expm1f(v3);
            }
            if (C) {
                if (m0 < M) *(float2*)&C[(size_t)m0 * ldc + n0] = make_float2(v0, v1);
                if (m0 + 8 < M) *(float2*)&C[(size_t)(m0 + 8) * ldc + n0] = make_float2(v2, v3);
            }
            if (Ch) {
                if (m0 < M) *(__half2*)&Ch[(size_t)m0 * ldc + n0] = __floats2half2_rn(v0, v1);
                if (m0 + 8 < M) *(__half2*)&Ch[(size_t)(m0 + 8) * ldc + n0] = __floats2half2_rn(v2, v3);
            }
        }
    }

    // fused attention-logit partials (raw acc)
    if (ss) {
        const int Hh = N >> 8;
        const int h = bn >> 8;
        const int cb0 = (bn & 255) + wn + (lane & 3) * 2;
#pragma unroll
        for (int mt = 0; mt < 2; mt++) {
            int m0 = bm + wr + mt * 16 + (lane >> 2);
            float ps0 = 0.f, pd0 = 0.f, ps1 = 0.f, pd1 = 0.f;
#pragma unroll
            for (int j = 0; j < 8; j++) {
                int cb = cb0 + j * 8;
                float a0 = av[h * 256 + cb], a1 = av[h * 256 + cb + 1];
                float d0 = bv[h * 256 + cb], d1 = bv[h * 256 + cb + 1];
                ps0 += acc[mt][j][0] * a0 + acc[mt][j][1] * a1;
                pd0 += acc[mt][j][0] * d0 + acc[mt][j][1] * d1;
                ps1 += acc[mt][j][2] * a0 + acc[mt][j][3] * a1;
                pd1 += acc[mt][j][2] * d0 + acc[mt][j][3] * d1;
            }
#pragma unroll
            for (int o = 1; o < 4; o <<= 1) {
                ps0 += __shfl_xor_sync(0xffffffffu, ps0, o);
                pd0 += __shfl_xor_sync(0xffffffffu, pd0, o);
                ps1 += __shfl_xor_sync(0xffffffffu, ps1, o);
                pd1 += __shfl_xor_sync(0xffffffffu, pd1, o);
            }
            if ((lane & 3) == 0) {
                if (m0 < M) {
                    atomicAdd(&ss[m0 * Hh + h], ps0);
                    atomicAdd(&sd[m0 * Hh + h], pd0);
                }
                if (m0 + 8 < M) {
                    atomicAdd(&ss[(m0 + 8) * Hh + h], ps1);
                    atomicAdd(&sd[(m0 + 8) * Hh + h], pd1);
                }
            }
        }
    }

    // fused influence partial (N == 128)
    if (yp) {
#pragma unroll
        for (int mt = 0; mt < 2; mt++) {
            int m0 = bm + wr + mt * 16 + (lane >> 2);
            float p0 = 0.f, p1 = 0.f;
#pragma unroll
            for (int j = 0; j < 8; j++) {
                int n0 = wn + j * 8 + (lane & 3) * 2;
                float w0 = wp2[n0], w1 = wp2[n0 + 1];
                float b0 = bp1[n0], b1e = bp1[n0 + 1];
                p0 += fmaxf(acc[mt][j][0] + b0, 0.f) * w0 + fmaxf(acc[mt][j][1] + b1e, 0.f) * w1;
                p1 += fmaxf(acc[mt][j][2] + b0, 0.f) * w0 + fmaxf(acc[mt][j][3] + b1e, 0.f) * w1;
            }
#pragma unroll
            for (int o = 1; o < 4; o <<= 1) {
                p0 += __shfl_xor_sync(0xffffffffu, p0, o);
                p1 += __shfl_xor_sync(0xffffffffu, p1, o);
            }
            if ((lane & 3) == 0) {
                if (m0 < M) atomicAdd(&yp[m0], p0);
                if (m0 + 8 < M) atomicAdd(&yp[m0 + 8], p1);
            }
        }
    }
}

// ---------------- CSR build ----------------
__global__ void k_deg_init(int n) {
    int i = blockIdx.x * blockDim.x + threadIdx.x;
    if (i < n) g_deg[i] = 1;
}
__global__ void k_deg_count(const int* __restrict__ dst, int e) {
    int i = blockIdx.x * blockDim.x + threadIdx.x;
    if (i < e) atomicAdd(&g_deg[dst[i]], 1);
}
__global__ void k_scan(int n) {
    __shared__ int sums[1024];
    int tid = threadIdx.x;
    int chunk = (n + 1023) / 1024;
    int lo = tid * chunk, hi = min(lo + chunk, n);
    int s = 0;
    for (int i = lo; i < hi; i++) s += g_deg[i];
    sums[tid] = s;
    __syncthreads();
    for (int d = 1; d < 1024; d <<= 1) {
        int v = (tid >= d) ? sums[tid - d] : 0;
        __syncthreads();
        sums[tid] += v;
        __syncthreads();
    }
    int base = (tid == 0) ? 0 : sums[tid - 1];
    for (int i = lo; i < hi; i++) {
        g_off[i] = base;
        g_cur[i] = base;
        base += g_deg[i];
    }
    if (tid == 1023) g_off[n] = sums[1023];
}
__global__ void k_fill(const int* __restrict__ src, const int* __restrict__ dst, int e, int n) {
    int i = blockIdx.x * blockDim.x + threadIdx.x;
    if (i >= e + n) return;
    int s, d;
    if (i < e) { s = src[i]; d = dst[i]; }
    else       { s = i - e;  d = i - e; }
    int pos = atomicAdd(&g_cur[d], 1);
    g_csrc[pos] = s;
}

// ---------------- layer-1 aggregation over x (4 heads share loads) ----------
// blockDim 384: 4 groups of 96 threads; PH=4 halves/thread (uint2).
__global__ void __launch_bounds__(384)
k_agg1x(const __half* __restrict__ xh, const float* __restrict__ ss,
        const float* __restrict__ sd, __half* __restrict__ aggx, int d0) {
    constexpr int CAP = 64, GSZ = 96, NG = 4;
    const int t = threadIdx.x;
    const int g = t / GSZ, gt = t % GSZ;
    const int gw = gt >> 5, lane = gt & 31;
    const int d = d0 + blockIdx.x * NG + g;
    const int base = g_off[d], deg = g_off[d + 1] - base;
    const int capped = min(deg, CAP);
    const int barid = g + 1;
    __shared__ __align__(16) float s_e[NG][CAP * 4];
    __shared__ int s_idx[NG][CAP];
    __shared__ float s_m[NG][4], s_inv[NG][4];
#define GBAR() asm volatile("bar.sync %0, %1;" :: "r"(barid), "r"(96) : "memory")

    // A: cache indices + raw lrelu logits
    {
        int jj = gt >> 2, h = gt & 3;
        float sdv = sd[d * 4 + h];
        for (int j0 = 0; j0 < capped; j0 += 24) {
            int j = j0 + jj;
            if (j < capped) {
                int s = g_csrc[base + j];
                if (h == 0) s_idx[g][j] = s;
                s_e[g][j * 4 + h] = lrelu(ss[s * 4 + h] + sdv);
            }
        }
    }
    GBAR();
    // B: max + denom; warp gw handles heads gw, gw+3
    for (int h = gw; h < 4; h += 3) {
        float sdv = sd[d * 4 + h];
        float mx = -1e30f;
        for (int j = lane; j < capped; j += 32) mx = fmaxf(mx, s_e[g][j * 4 + h]);
        for (int j = CAP + lane; j < deg; j += 32) {
            int s = g_csrc[base + j];
            mx = fmaxf(mx, lrelu(ss[s * 4 + h] + sdv));
        }
#pragma unroll
        for (int o = 16; o; o >>= 1) mx = fmaxf(mx, __shfl_xor_sync(0xffffffffu, mx, o));
        float sm = 0.f;
        for (int j = lane; j < capped; j += 32) sm += expf(s_e[g][j * 4 + h] - mx);
        for (int j = CAP + lane; j < deg; j += 32) {
            int s = g_csrc[base + j];
            sm += expf(lrelu(ss[s * 4 + h] + sdv) - mx);
        }
#pragma unroll
        for (int o = 16; o; o >>= 1) sm += __shfl_xor_sync(0xffffffffu, sm, o);
        if (lane == 0) { s_m[g][h] = mx; s_inv[g][h] = 1.f / (sm + 1e-16f); }
    }
    GBAR();
    // C: logits -> weights
    {
        int jj = gt >> 2, h = gt & 3;
        float mh = s_m[g][h], iv = s_inv[g][h];
        for (int j0 = 0; j0 < capped; j0 += 24) {
            int j = j0 + jj;
            if (j < capped) s_e[g][j * 4 + h] = expf(s_e[g][j * 4 + h] - mh) * iv;
        }
    }
    GBAR();

    float acc[4][4];
#pragma unroll
    for (int h = 0; h < 4; h++)
#pragma unroll
        for (int k = 0; k < 4; k++) acc[h][k] = 0.f;
    const int* sidx = &s_idx[g][0];
    const __half* fb = xh + gt * 4;

    // D: one uint2 x-load per edge feeds all 4 heads; 4-deep prefetch
    {
        uint2 b0 = make_uint2(0, 0), b1 = b0, b2 = b0, b3 = b0;
        if (capped > 0) b0 = *(const uint2*)(fb + (size_t)sidx[0] * FIN);
        if (capped > 1) b1 = *(const uint2*)(fb + (size_t)sidx[1] * FIN);
        if (capped > 2) b2 = *(const uint2*)(fb + (size_t)sidx[2] * FIN);
        if (capped > 3) b3 = *(const uint2*)(fb + (size_t)sidx[3] * FIN);
        int j = 0;
        for (; j + 4 <= capped; j += 4) {
            uint2 v[4] = {b0, b1, b2, b3};
            if (j + 4 < capped) b0 = *(const uint2*)(fb + (size_t)sidx[j + 4] * FIN);
            if (j + 5 < capped) b1 = *(const uint2*)(fb + (size_t)sidx[j + 5] * FIN);
            if (j + 6 < capped) b2 = *(const uint2*)(fb + (size_t)sidx[j + 6] * FIN);
            if (j + 7 < capped) b3 = *(const uint2*)(fb + (size_t)sidx[j + 7] * FIN);
#pragma unroll
            for (int e = 0; e < 4; e++) {
                float4 w = *(const float4*)&s_e[g][(j + e) * 4];
                float2 f0 = __half22float2(*(const __half2*)&v[e].x);
                float2 f1 = __half22float2(*(const __half2*)&v[e].y);
                acc[0][0] += f0.x * w.x; acc[0][1] += f0.y * w.x; acc[0][2] += f1.x * w.x; acc[0][3] += f1.y * w.x;
                acc[1][0] += f0.x * w.y; acc[1][1] += f0.y * w.y; acc[1][2] += f1.x * w.y; acc[1][3] += f1.y * w.y;
                acc[2][0] += f0.x * w.z; acc[2][1] += f0.y * w.z; acc[2][2] += f1.x * w.z; acc[2][3] += f1.y * w.z;
                acc[3][0] += f0.x * w.w; acc[3][1] += f0.y * w.w; acc[3][2] += f1.x * w.w; acc[3][3] += f1.y * w.w;
            }
        }
        uint2 rb[3] = {b0, b1, b2};
        for (int r = 0; r < 3 && j + r < capped; r++) {
            float4 w = *(const float4*)&s_e[g][(j + r) * 4];
            float2 f0 = __half22float2(*(const __half2*)&rb[r].x);
            float2 f1 = __half22float2(*(const __half2*)&rb[r].y);
            acc[0][0] += f0.x * w.x; acc[0][1] += f0.y * w.x; acc[0][2] += f1.x * w.x; acc[0][3] += f1.y * w.x;
            acc[1][0] += f0.x * w.y; acc[1][1] += f0.y * w.y; acc[1][2] += f1.x * w.y; acc[1][3] += f1.y * w.y;
            acc[2][0] += f0.x * w.z; acc[2][1] += f0.y * w.z; acc[2][2] += f1.x * w.z; acc[2][3] += f1.y * w.z;
            acc[3][0] += f0.x * w.w; acc[3][1] += f0.y * w.w; acc[3][2] += f1.x * w.w; acc[3][3] += f1.y * w.w;
        }
    }
    // E: overflow (rare)
    if (deg > CAP) {
        for (int j = CAP; j < deg; j++) {
            int s = g_csrc[base + j];
            uint2 v = *(const uint2*)(fb + (size_t)s * FIN);
            float2 f0 = __half22float2(*(const __half2*)&v.x);
            float2 f1 = __half22float2(*(const __half2*)&v.y);
#pragma unroll
            for (int h = 0; h < 4; h++) {
                float w = expf(lrelu(ss[s * 4 + h] + sd[d * 4 + h]) - s_m[g][h]) * s_inv[g][h];
                acc[h][0] += f0.x * w; acc[h][1] += f0.y * w;
                acc[h][2] += f1.x * w; acc[h][3] += f1.y * w;
            }
        }
    }
    // epilogue: write 4 head planes
#pragma unroll
    for (int h = 0; h < 4; h++) {
        __half2 p0 = __floats2half2_rn(acc[h][0], acc[h][1]);
        __half2 p1 = __floats2half2_rn(acc[h][2], acc[h][3]);
        __half2* dst = (__half2*)(aggx + (size_t)h * NN * FIN + (size_t)d * FIN + gt * 4);
        dst[0] = p0; dst[1] = p1;
    }
#undef GBAR
}

// ---------------- layer-2 grouped aggregation (H=1, C=256, GSZ=64) ----------
__device__ __forceinline__ void acc4(float* a, uint2 v, float w) {
    float2 f;
    f = __half22float2(*(__half2*)&v.x); a[0] += f.x * w; a[1] += f.y * w;
    f = __half22float2(*(__half2*)&v.y); a[2] += f.x * w; a[3] += f.y * w;
}
__global__ void __launch_bounds__(256)
k_agg2(const __half* __restrict__ feat, const float* __restrict__ ss,
       const float* __restrict__ sd, const float* __restrict__ bias,
       float* __restrict__ out, __half* __restrict__ oh, int d0) {
    constexpr int NG = 4, CAP = 64, GSZ = 64, HC = F2;
    const int t = threadIdx.x;
    const int g = t / GSZ, gt = t % GSZ;
    const int gw = gt >> 5, lane = gt & 31;
    const int d = d0 + blockIdx.x * NG + g;
    const int base = g_off[d], deg = g_off[d + 1] - base;
    const int capped = min(deg, CAP);
    const int barid = g + 1;
    __shared__ float s_e[NG][CAP];
    __shared__ int s_idx[NG][CAP];
    __shared__ float s_m[NG], s_inv[NG];
#define GBAR() asm volatile("bar.sync %0, %1;" :: "r"(barid), "r"(64) : "memory")
    {
        const float sdv = sd[d];
        for (int j = gt; j < capped; j += GSZ) {
            int s = g_csrc[base + j];
            s_idx[g][j] = s;
            s_e[g][j] = lrelu(ss[s] + sdv);
        }
    }
    GBAR();
    if (gw == 0) {
        const float sdv = sd[d];
        float mx = -1e30f;
        for (int j = lane; j < capped; j += 32) mx = fmaxf(mx, s_e[g][j]);
        for (int j = CAP + lane; j < deg; j += 32) {
            int s = g_csrc[base + j];
            mx = fmaxf(mx, lrelu(ss[s] + sdv));
        }
#pragma unroll
        for (int o = 16; o; o >>= 1) mx = fmaxf(mx, __shfl_xor_sync(0xffffffffu, mx, o));
        float sm = 0.f;
        for (int j = lane; j < capped; j += 32) sm += expf(s_e[g][j] - mx);
        for (int j = CAP + lane; j < deg; j += 32) {
            int s = g_csrc[base + j];
            sm += expf(lrelu(ss[s] + sdv) - mx);
        }
#pragma unroll
        for (int o = 16; o; o >>= 1) sm += __shfl_xor_sync(0xffffffffu, sm, o);
        if (lane == 0) { s_m[g] = mx; s_inv[g] = 1.f / (sm + 1e-16f); }
    }
    GBAR();
    {
        const float mh = s_m[g], iv = s_inv[g];
        for (int j = gt; j < capped; j += GSZ) s_e[g][j] = expf(s_e[g][j] - mh) * iv;
    }
    GBAR();

    float acc[4] = {0, 0, 0, 0};
    const float* we = &s_e[g][0];
    const int* sidx = &s_idx[g][0];
    const __half* fb = feat + gt * 4;
    uint2 b0 = make_uint2(0, 0), b1 = b0, b2 = b0, b3 = b0;
    if (capped > 0) b0 = *(const uint2*)(fb + (size_t)sidx[0] * HC);
    if (capped > 1) b1 = *(const uint2*)(fb + (size_t)sidx[1] * HC);
    if (capped > 2) b2 = *(const uint2*)(fb + (size_t)sidx[2] * HC);
    if (capped > 3) b3 = *(const uint2*)(fb + (size_t)sidx[3] * HC);
    int j = 0;
    for (; j + 4 <= capped; j += 4) {
        float w0 = we[j + 0], w1 = we[j + 1], w2 = we[j + 2], w3 = we[j + 3];
        uint2 v0 = b0, v1 = b1, v2 = b2, v3 = b3;
        if (j + 4 < capped) b0 = *(const uint2*)(fb + (size_t)sidx[j + 4] * HC);
        if (j + 5 < capped) b1 = *(const uint2*)(fb + (size_t)sidx[j + 5] * HC);
        if (j + 6 < capped) b2 = *(const uint2*)(fb + (size_t)sidx[j + 6] * HC);
        if (j + 7 < capped) b3 = *(const uint2*)(fb + (size_t)sidx[j + 7] * HC);
        acc4(acc, v0, w0); acc4(acc, v1, w1); acc4(acc, v2, w2); acc4(acc, v3, w3);
    }
    if (j     < capped) acc4(acc, b0, we[j + 0]);
    if (j + 1 < capped) acc4(acc, b1, we[j + 1]);
    if (j + 2 < capped) acc4(acc, b2, we[j + 2]);
    if (deg > CAP) {
        const float mh = s_m[g], iv = s_inv[g];
        const float sdv = sd[d];
        for (int jj = CAP; jj < deg; jj++) {
            int s = g_csrc[base + jj];
            float w = expf(lrelu(ss[s] + sdv) - mh) * iv;
            acc4(acc, *(const uint2*)(feat + (size_t)s * HC + gt * 4), w);
        }
    }
    const int c0 = gt * 4;
    float vv[4];
#pragma unroll
    for (int k = 0; k < 4; k++) {
        float v = acc[k] + bias[c0 + k];
        vv[k] = v > 0.f ? v : expm1f(v);
    }
    *(float2*)&out[(size_t)d * HC + c0] = make_float2(vv[0], vv[1]);
    *(float2*)&out[(size_t)d * HC + c0 + 2] = make_float2(vv[2], vv[3]);
    *(__half2*)&oh[(size_t)d * HC + c0] = __floats2half2_rn(vv[0], vv[1]);
    *(__half2*)&oh[(size_t)d * HC + c0 + 2] = __floats2half2_rn(vv[2], vv[3]);
#undef GBAR
}

// ---------------- graph mean + sigmoid ----------------
__global__ void k_zero_gf(float* gf) { gf[threadIdx.x] = 0.f; }
__global__ void k_colsum(const float* __restrict__ h, float* __restrict__ gf) {
    float acc = 0.f;
    int t = threadIdx.x;
    for (int r = blockIdx.x; r < NN; r += gridDim.x) acc += h[(size_t)r * F2 + t];
    atomicAdd(&gf[t], acc);
}
__global__ void k_scale_gf(float* gf) { gf[threadIdx.x] *= (1.0f / (float)NN); }
__global__ void k_sigmoid(const float* __restrict__ yp, const float* __restrict__ bp2,
                          float* __restrict__ infl, int n, int i0) {
    int i = blockIdx.x * blockDim.x + threadIdx.x;
    if (i < n) infl[i0 + i] = 1.f / (1.f + expf(-(yp[i0 + i] + bp2[0])));
}

// ---------------- host: tensor-map builder ----------------
typedef CUresult (*PFN_encodeTiled)(
    CUtensorMap*, CUtensorMapDataType, cuuint32_t, void*,
    const cuuint64_t*, const cuuint64_t*, const cuuint32_t*, const cuuint32_t*,
    CUtensorMapInterleave, CUtensorMapSwizzle, CUtensorMapL2promotion,
    CUtensorMapFloatOOBfill);

static CUtensorMap make_map(PFN_encodeTiled enc, void* base, int K, int rows) {
    CUtensorMap m;
    cuuint64_t dims[2]    = {(cuuint64_t)K, (cuuint64_t)rows};
    cuuint64_t strides[1] = {(cuuint64_t)K * 2};
    cuuint32_t box[2]     = {64, 128};
    cuuint32_t es[2]      = {1, 1};
    enc(&m, CU_TENSOR_MAP_DATA_TYPE_FLOAT16, 2, base, dims, strides, box, es,
        CU_TENSOR_MAP_INTERLEAVE_NONE, CU_TENSOR_MAP_SWIZZLE_128B,
        CU_TENSOR_MAP_L2_PROMOTION_L2_128B, CU_TENSOR_MAP_FLOAT_OOB_FILL_NONE);
    return m;
}

// ---------------- launch ----------------
extern "C" void kernel_launch(void* const* d_in, const int* in_sizes, int n_in,
                              void* d_out, int out_size) {
    const float* x   = (const float*)d_in[0];
    const int*   eidx = (const int*)d_in[1];
    const float* W1  = (const float*)d_in[2];
    const float* as1 = (const float*)d_in[3];
    const float* ad1 = (const float*)d_in[4];
    const float* b1  = (const float*)d_in[5];
    const float* W2  = (const float*)d_in[6];
    const float* as2 = (const float*)d_in[7];
    const float* ad2 = (const float*)d_in[8];
    const float* b2  = (const float*)d_in[9];
    const float* Wp1 = (const float*)d_in[10];
    const float* bp1 = (const float*)d_in[11];
    const float* Wp2 = (const float*)d_in[12];
    const float* bp2 = (const float*)d_in[13];

    const int* src = eidx;
    const int* dst = eidx + EE;

    float* out   = (float*)d_out;
    float* out_h = out;
    float* out_g = out + (size_t)NN * F2;
    float* out_i = out_g + F2;

    float *p_yp, *p_ss1, *p_sd1, *p_ss2, *p_sd2, *p_wa;
    __half *p_xh, *p_aggx, *p_w1h4, *p_o1h, *p_w2h, *p_h2h, *p_hh, *p_wph;
    cudaGetSymbolAddress((void**)&p_yp, g_yp);
    cudaGetSymbolAddress((void**)&p_ss1, g_ss1);
    cudaGetSymbolAddress((void**)&p_sd1, g_sd1);
    cudaGetSymbolAddress((void**)&p_ss2, g_ss2);
    cudaGetSymbolAddress((void**)&p_sd2, g_sd2);
    cudaGetSymbolAddress((void**)&p_wa,  g_wa);
    cudaGetSymbolAddress((void**)&p_xh,  g_xh);
    cudaGetSymbolAddress((void**)&p_aggx, g_aggx);
    cudaGetSymbolAddress((void**)&p_w1h4, g_w1h4);
    cudaGetSymbolAddress((void**)&p_o1h, g_o1h);
    cudaGetSymbolAddress((void**)&p_w2h, g_w2h);
    cudaGetSymbolAddress((void**)&p_h2h, g_h2h);
    cudaGetSymbolAddress((void**)&p_hh,  g_hh);
    cudaGetSymbolAddress((void**)&p_wph, g_wph);

    PFN_encodeTiled enc = nullptr;
    cudaGetDriverEntryPoint("cuTensorMapEncodeTiled", (void**)&enc, cudaEnableDefault);

    CUtensorMap mAX[4], mBW1[4];
    for (int h = 0; h < 4; h++) {
        mAX[h]  = make_map(enc, p_aggx + (size_t)h * NN * FIN, FIN, NN);
        mBW1[h] = make_map(enc, p_w1h4 + (size_t)h * 256 * FIN, FIN, 256);
    }
    CUtensorMap mA2 = make_map(enc, p_o1h, F1, NN);
    CUtensorMap mB2 = make_map(enc, p_w2h, F1, F2);
    CUtensorMap mA3 = make_map(enc, p_hh,  F2, NN);
    CUtensorMap mB3 = make_map(enc, p_wph, F2, PHID);

    cudaFuncSetAttribute(hgemm_tma, cudaFuncAttributeMaxDynamicSharedMemorySize, TG_SMEM);

    static cudaStream_t s1 = nullptr;
    static cudaEvent_t evF1 = nullptr, evWA = nullptr, evJ1 = nullptr, evA1lo = nullptr,
                       evS1a = nullptr, evA2lo = nullptr, evA2hi = nullptr, evJ2 = nullptr;
    if (!s1) {
        cudaStreamCreateWithFlags(&s1, cudaStreamNonBlocking);
        cudaEventCreateWithFlags(&evF1,  cudaEventDisableTiming);
        cudaEventCreateWithFlags(&evWA,  cudaEventDisableTiming);
        cudaEventCreateWithFlags(&evJ1,  cudaEventDisableTiming);
        cudaEventCreateWithFlags(&evA1lo, cudaEventDisableTiming);
        cudaEventCreateWithFlags(&evS1a, cudaEventDisableTiming);
        cudaEventCreateWithFlags(&evA2lo, cudaEventDisableTiming);
        cudaEventCreateWithFlags(&evA2hi, cudaEventDisableTiming);
        cudaEventCreateWithFlags(&evJ2,  cudaEventDisableTiming);
    }

    // ---- side fork: wa + weight casts + CSR ----
    cudaEventRecord(evF1, 0);
    cudaStreamWaitEvent(s1, evF1, 0);
    k_wa1<<<(8 * FIN + 255) / 256, 256, 0, s1>>>(W1, as1, ad1, p_wa);
    cudaEventRecord(evWA, s1);
    k_castT4<<<(FIN * F1 + 255) / 256, 256, 0, s1>>>(W1, p_w1h4);
    k_castT<<<(F1 * F2 + 255) / 256, 256, 0, s1>>>(W2, p_w2h, F1, F2);
    k_castT<<<(F2 * PHID + 255) / 256, 256, 0, s1>>>(Wp1, p_wph, F2, PHID);
    k_deg_init <<<(NN + 255) / 256, 256, 0, s1>>>(NN);
    k_deg_count<<<(EE + 255) / 256, 256, 0, s1>>>(dst, EE);
    k_scan<<<1, 1024, 0, s1>>>(NN);
    k_fill<<<(ETOT + 255) / 256, 256, 0, s1>>>(src, dst, EE, NN);
    cudaEventRecord(evJ1, s1);

    // ---- main: zeros, cast x, logits from x ----
    k_zero3<<<(NN + 255) / 256, 256>>>(p_ss2, p_sd2, p_yp, NN);
    k_cast <<<(NN * FIN + 255) / 256, 256>>>(x, p_xh, NN * FIN);
    cudaStreamWaitEvent(0, evWA, 0);
    k_slogits_x<<<(NN * 32 + 255) / 256, 256>>>(x, p_wa, p_ss1, p_sd1);
    cudaStreamWaitEvent(0, evJ1, 0);

    // ---- agg1x split-pipeline with per-head GEMM1' + GEMM2 ----
    k_agg1x<<<NSPLIT / 4, 384>>>(p_xh, p_ss1, p_sd1, p_aggx, 0);
    cudaEventRecord(evA1lo, 0);
    cudaStreamWaitEvent(s1, evA1lo, 0);
    for (int h = 0; h < 4; h++)
        hgemm_tma<<<dim3(2, TLO), 256, TG_SMEM, s1>>>(mAX[h], mBW1[h], nullptr,
            p_o1h + h * 256, NN, 256, FIN, 0, F1, b1 + h * 256,
            nullptr, nullptr, nullptr, nullptr, nullptr, nullptr, nullptr);
    hgemm_tma<<<dim3(F2 / 128, TLO), 256, TG_SMEM, s1>>>(mA2, mB2, nullptr, p_h2h,
        NN, F2, F1, 0, F2, nullptr, p_ss2, p_sd2, as2, ad2, nullptr, nullptr, nullptr);
    cudaEventRecord(evS1a, s1);

    k_agg1x<<<(NN - NSPLIT) / 4, 384>>>(p_xh, p_ss1, p_sd1, p_aggx, NSPLIT);
    for (int h = 0; h < 4; h++)
        hgemm_tma<<<dim3(2, THI), 256, TG_SMEM>>>(mAX[h], mBW1[h], nullptr,
            p_o1h + h * 256, NN, 256, FIN, TLO, F1, b1 + h * 256,
            nullptr, nullptr, nullptr, nullptr, nullptr, nullptr, nullptr);
    hgemm_tma<<<dim3(F2 / 128, THI), 256, TG_SMEM>>>(mA2, mB2, nullptr, p_h2h,
        NN, F2, F1, TLO, F2, nullptr, p_ss2, p_sd2, as2, ad2, nullptr, nullptr, nullptr);
    cudaStreamWaitEvent(0, evS1a, 0);

    // ---- agg2 split-pipeline with GEMM3 (fused influence) ----
    k_agg2<<<NSPLIT / 4, 256>>>(p_h2h, p_ss2, p_sd2, b2, out_h, p_hh, 0);
    cudaEventRecord(evA2lo, 0);
    cudaStreamWaitEvent(s1, evA2lo, 0);
    hgemm_tma<<<dim3(1, TLO), 256, TG_SMEM, s1>>>(mA3, mB3, nullptr, nullptr,
        NN, PHID, F2, 0, PHID, nullptr, nullptr, nullptr, nullptr, nullptr, p_yp, bp1, Wp2);
    k_sigmoid<<<(NSPLIT + 255) / 256, 256, 0, s1>>>(p_yp, bp2, out_i, NSPLIT, 0);

    k_agg2<<<(NN - NSPLIT) / 4, 256>>>(p_h2h, p_ss2, p_sd2, b2, out_h, p_hh, NSPLIT);
    cudaEventRecord(evA2hi, 0);

    cudaStreamWaitEvent(s1, evA2hi, 0);
    k_zero_gf<<<1, F2, 0, s1>>>(out_g);
    k_colsum<<<160, F2, 0, s1>>>(out_h, out_g);
    k_scale_gf<<<1, F2, 0, s1>>>(out_g);
    cudaEventRecord(evJ2, s1);

    hgemm_tma<<<dim3(1, THI), 256, TG_SMEM>>>(mA3, mB3, nullptr, nullptr,
        NN, PHID, F2, TLO, PHID, nullptr, nullptr, nullptr, nullptr, nullptr, p_yp, bp1, Wp2);
    k_sigmoid<<<(NN - NSPLIT + 255) / 256, 256>>>(p_yp, bp2, out_i, NN - NSPLIT, NSPLIT);
    cudaStreamWaitEvent(0, evJ2, 0);
}